// round 16
// baseline (speedup 1.0000x reference)
#include <cuda_runtime.h>
#include <math.h>

#define NELEM  16384
#define KSEL   8192
#define NT     1024
#define NBINS  16384
#define SH     12
#define LOBITS 0x3B800000u   // float bits of 2^-8; lower scores clamp to bin 0

// ---- persistent scratch (zero-init at load; maintained across graph replays) ----
__device__ __align__(16) unsigned int g_hist[NBINS];   // re-zeroed post-bar2 each run
__device__ __align__(16) uint2 g_cand[NELEM + 8];      // +8: sentinel-safe batch reads
__device__ unsigned int g_ccount;                      // reset pre-bar1 each run

__device__ __forceinline__ void cbar()
{
    // HW cluster barrier; arrive has cluster-scope release semantics, covering
    // prior gmem writes/REDs by cluster threads (validated R6/R15).
    asm volatile("barrier.cluster.arrive.aligned;" ::: "memory");
    asm volatile("barrier.cluster.wait.aligned;"   ::: "memory");
}

// ================= shared body, templated on cluster size =================
template <int NC>
__device__ __forceinline__ void ca_body(const float* __restrict__ x,
                                        const float* __restrict__ w7,
                                        float* __restrict__ out)
{
    constexpr int CPB = NELEM / NC;     // elements per CTA
    constexpr int EPT = CPB / NT;       // 1 (NC=16) or 2 (NC=8)

    __shared__ float        sx[CPB + 6];
    __shared__ float        swt[7];
    __shared__ unsigned int sm_w[32];
    __shared__ unsigned int s_w0, s_w1;

    const int tid  = threadIdx.x;
    const int lane = tid & 31;
    const int wid  = tid >> 5;
    const int E0   = (int)blockIdx.x * CPB;
    const int l0   = tid * EPT;
    const int e0   = E0 + l0;

    if (e0 == 0)  g_ccount = 0u;        // ordered before registrations by bar1
    if (tid < 7)  swt[tid] = __ldg(w7 + tid);

    // ---- stage x tile (+3 halo each side) ----
    if (EPT == 2) {
        const float2 xv = *(const float2*)(x + e0);
        sx[3 + l0]     = xv.x;
        sx[3 + l0 + 1] = xv.y;
    } else {
        sx[3 + l0] = __ldg(x + e0);
    }
    if (tid < 3) {
        const int gl = E0 - 3 + tid;
        sx[tid] = (gl >= 0) ? __ldg(x + gl) : 0.0f;
        const int gr = E0 + CPB + tid;
        sx[3 + CPB + tid] = (gr < NELEM) ? __ldg(x + gr) : 0.0f;
    }
    __syncthreads();

    const float w0 = swt[0], w1 = swt[1], w2 = swt[2], w3 = swt[3],
                w4 = swt[4], w5 = swt[5], w6 = swt[6];

    // ---- conv 'same' + sigmoid (accurate expf protects selection boundary) ----
    float        xv[EPT], sc[EPT];
    unsigned int v[EPT];
    int          bin[EPT];
    #pragma unroll
    for (int r = 0; r < EPT; ++r) {
        const int li = l0 + r;
        float y = sx[li] * w0;
        y = fmaf(sx[li + 1], w1, y);
        y = fmaf(sx[li + 2], w2, y);
        y = fmaf(sx[li + 3], w3, y);
        y = fmaf(sx[li + 4], w4, y);
        y = fmaf(sx[li + 5], w5, y);
        y = fmaf(sx[li + 6], w6, y);
        const float s = 1.0f / (1.0f + expf(-y));
        xv[r] = sx[li + 3];
        sc[r] = s;
        v[r]  = __float_as_uint(s);     // positive: bit order == value order
        const int d = (int)(v[r] - LOBITS);
        bin[r] = d < 0 ? 0 : (d >> SH); // s < 1.0 => bin <= 16383
    }
    if (EPT == 2) *(float2*)(out + NELEM + e0) = make_float2(sc[0], sc[1]);
    else          out[NELEM + e0] = sc[0];

    // ---- global histogram (merge adjacent same-bin REDs when EPT==2) ----
    if (EPT == 2 && bin[0] == bin[1]) {
        atomicAdd(&g_hist[bin[0]], 2u);
    } else {
        #pragma unroll
        for (int r = 0; r < EPT; ++r) atomicAdd(&g_hist[bin[r]], 1u);
    }

    cbar();   // ---- bar1: histogram complete ----

    // ---- redundant per-CTA prefix scan over 16384 bins (16/thread, registers) ----
    {
        unsigned int h[16];
        {
            const uint4* hp = (const uint4*)(g_hist + tid * 16);
            uint4 q0 = __ldcg(hp + 0), q1 = __ldcg(hp + 1),
                  q2 = __ldcg(hp + 2), q3 = __ldcg(hp + 3);
            h[0]=q0.x;  h[1]=q0.y;  h[2]=q0.z;  h[3]=q0.w;
            h[4]=q1.x;  h[5]=q1.y;  h[6]=q1.z;  h[7]=q1.w;
            h[8]=q2.x;  h[9]=q2.y;  h[10]=q2.z; h[11]=q2.w;
            h[12]=q3.x; h[13]=q3.y; h[14]=q3.z; h[15]=q3.w;
        }
        unsigned int local = 0;
        #pragma unroll
        for (int q = 0; q < 16; ++q) local += h[q];

        unsigned int inc = local;
        #pragma unroll
        for (int o = 1; o < 32; o <<= 1) {
            unsigned int t = __shfl_up_sync(0xffffffffu, inc, o);
            if (lane >= o) inc += t;
        }
        if (lane == 31) sm_w[wid] = inc;
        __syncthreads();
        if (wid == 0) {
            unsigned int wsum = sm_w[lane];
            unsigned int winc = wsum;
            #pragma unroll
            for (int o = 1; o < 32; o <<= 1) {
                unsigned int t = __shfl_up_sync(0xffffffffu, winc, o);
                if (lane >= o) winc += t;
            }
            sm_w[lane] = winc - wsum;    // exclusive warp base
        }
        __syncthreads();
        const unsigned int base = sm_w[wid] + inc - local;

        if (base < KSEL && base + local >= KSEL) {   // exactly one thread; regs only
            unsigned int c = base;
            #pragma unroll
            for (int q = 0; q < 16; ++q) {
                if (c + h[q] >= KSEL) {
                    s_w0 = (unsigned)(tid * 16 + q) | ((KSEL - c) << 16);  // bstar|jkeep<<16
                    s_w1 = h[q];                                            // hcount
                    break;
                }
                c += h[q];
            }
        }
    }
    __syncthreads();
    const int          bstar  = (int)(s_w0 & 0xFFFFu);
    const unsigned int jkeep  = s_w0 >> 16;
    const unsigned int hcount = s_w1;

    // ---- register boundary candidates (expected ~10-30) ----
    bool anyb = false;
    #pragma unroll
    for (int r = 0; r < EPT; ++r) {
        if (bin[r] == bstar) {
            anyb = true;
            const unsigned int t = atomicAdd(&g_ccount, 1u);
            g_cand[t] = make_uint2(v[r], (unsigned)(e0 + r));
        }
    }

    cbar();   // ---- bar2: candidates + all hist reads complete ----

    // hist re-zero for next replay (all readers passed bar2)
    #pragma unroll
    for (int i = 0; i < NBINS / NC / NT; ++i)
        g_hist[(int)blockIdx.x * (NBINS / NC) + i * NT + tid] = 0u;

    // ---- exact stable rank among candidates + emit new_x ----
    float o[EPT];
    #pragma unroll
    for (int r = 0; r < EPT; ++r)
        o[r] = (bin[r] < bstar) ? xv[r] * (sc[r] + 1.0f) : 0.0f;

    if (anyb) {
        unsigned int rk[EPT];
        #pragma unroll
        for (int r = 0; r < EPT; ++r) rk[r] = 0;
        for (unsigned int c = 0; c < hcount; c += 4) {     // 4 independent loads/iter
            uint2 cd[4];
            #pragma unroll
            for (int j = 0; j < 4; ++j) {
                const unsigned int idx = (c + (unsigned)j < hcount) ? c + (unsigned)j : 0u;
                cd[j] = __ldcg(&g_cand[idx]);
            }
            #pragma unroll
            for (int j = 0; j < 4; ++j) {
                if (c + (unsigned)j < hcount) {
                    #pragma unroll
                    for (int r = 0; r < EPT; ++r)
                        rk[r] += (cd[j].x < v[r]) ||
                                 (cd[j].x == v[r] && cd[j].y < (unsigned)(e0 + r));
                }
            }
        }
        #pragma unroll
        for (int r = 0; r < EPT; ++r)
            if (bin[r] == bstar)
                o[r] = (rk[r] < jkeep) ? xv[r] * (sc[r] + 1.0f) : 0.0f;
    }
    if (EPT == 2) *(float2*)(out + e0) = make_float2(o[0], o[1]);
    else          out[e0] = o[0];
}

// 16-CTA variant: cluster dims supplied at launch (nonportable size)
__global__ __launch_bounds__(NT, 1)
void ca_c16(const float* __restrict__ x, const float* __restrict__ w7,
            float* __restrict__ out)
{
    ca_body<16>(x, w7, out);
}

// 8-CTA fallback: compile-time portable cluster
__global__ __launch_bounds__(NT, 1) __cluster_dims__(8, 1, 1)
void ca_c8(const float* __restrict__ x, const float* __restrict__ w7,
           float* __restrict__ out)
{
    ca_body<8>(x, w7, out);
}

extern "C" void kernel_launch(void* const* d_in, const int* in_sizes, int n_in,
                              void* d_out, int out_size)
{
    const float* x = (const float*)d_in[0];
    const float* w = (const float*)d_in[1];
    if (n_in >= 2 && in_sizes[0] == 7) {   // defensive input-order check
        const float* t = x; x = w; w = t;
    }
    float* out = (float*)d_out;

    // Try nonportable cluster of 16 (pure queries — capture-safe, deterministic)
    cudaFuncSetAttribute(ca_c16, cudaFuncAttributeNonPortableClusterSizeAllowed, 1);

    cudaLaunchConfig_t cfg = {};
    cfg.gridDim       = dim3(16, 1, 1);
    cfg.blockDim      = dim3(NT, 1, 1);
    cfg.dynamicSmemBytes = 0;
    cfg.stream        = 0;
    cudaLaunchAttribute at[1];
    at[0].id = cudaLaunchAttributeClusterDimension;
    at[0].val.clusterDim.x = 16;
    at[0].val.clusterDim.y = 1;
    at[0].val.clusterDim.z = 1;
    cfg.attrs    = at;
    cfg.numAttrs = 1;

    int nclus = 0;
    cudaError_t q = cudaOccupancyMaxActiveClusters(&nclus, ca_c16, &cfg);
    if (q == cudaSuccess && nclus >= 1) {
        cudaLaunchKernelEx(&cfg, ca_c16, x, w, out);
    } else {
        cudaGetLastError();            // clear any sticky query error
        ca_c8<<<8, NT>>>(x, w, out);   // proven champion fallback
    }
}

// round 17
// speedup vs baseline: 1.0544x; 1.0544x over previous
#include <cuda_runtime.h>
#include <math.h>

#define NELEM  16384
#define KSEL   8192
#define NT     1024
#define NBINS  16384
#define WORDS  (NBINS / 2)     // packed u16 counters, 2 bins per u32
#define SH     12
#define LOBITS 0x3B800000u     // float bits of 2^-8; lower scores clamp to bin 0
#define CANDS  512             // smem staging capacity (candidates)

// ---- persistent scratch (zero-init at load; maintained across graph replays) ----
__device__ __align__(16) unsigned int g_hist[WORDS];   // re-zeroed post-bar2 each run
__device__ __align__(16) uint2 g_cand[NELEM + 8];
__device__ unsigned int g_ccount;                      // reset pre-bar1 each run

__device__ __forceinline__ void cbar()
{
    // HW cluster barrier; arrive has cluster-scope release semantics, covering
    // prior gmem writes/REDs by cluster threads (validated R6/R15/R16).
    asm volatile("barrier.cluster.arrive.aligned;" ::: "memory");
    asm volatile("barrier.cluster.wait.aligned;"   ::: "memory");
}

// ================= shared body, templated on cluster size =================
template <int NC>
__device__ __forceinline__ void ca_body(const float* __restrict__ x,
                                        const float* __restrict__ w7,
                                        float* __restrict__ out)
{
    constexpr int CPB = NELEM / NC;     // elements per CTA
    constexpr int EPT = CPB / NT;       // 1 (NC=16) or 2 (NC=8)

    __shared__ float        sx[CPB + 6];
    __shared__ float        swt[7];
    __shared__ unsigned int sm_w[32];
    __shared__ unsigned int s_w0, s_w1;
    __shared__ __align__(8) uint2 s_cand[CANDS];

    const int tid  = threadIdx.x;
    const int lane = tid & 31;
    const int wid  = tid >> 5;
    const int E0   = (int)blockIdx.x * CPB;
    const int l0   = tid * EPT;
    const int e0   = E0 + l0;

    if (e0 == 0)  g_ccount = 0u;        // ordered before registrations by bar1
    if (tid < 7)  swt[tid] = __ldg(w7 + tid);

    // ---- stage x tile (+3 halo each side) ----
    if (EPT == 2) {
        const float2 xv = *(const float2*)(x + e0);
        sx[3 + l0]     = xv.x;
        sx[3 + l0 + 1] = xv.y;
    } else {
        sx[3 + l0] = __ldg(x + e0);
    }
    if (tid < 3) {
        const int gl = E0 - 3 + tid;
        sx[tid] = (gl >= 0) ? __ldg(x + gl) : 0.0f;
        const int gr = E0 + CPB + tid;
        sx[3 + CPB + tid] = (gr < NELEM) ? __ldg(x + gr) : 0.0f;
    }
    __syncthreads();

    const float w0 = swt[0], w1 = swt[1], w2 = swt[2], w3 = swt[3],
                w4 = swt[4], w5 = swt[5], w6 = swt[6];

    // ---- conv 'same' + sigmoid (accurate expf protects selection boundary) ----
    float        xv[EPT], sc[EPT];
    unsigned int v[EPT];
    int          bin[EPT];
    #pragma unroll
    for (int r = 0; r < EPT; ++r) {
        const int li = l0 + r;
        float y = sx[li] * w0;
        y = fmaf(sx[li + 1], w1, y);
        y = fmaf(sx[li + 2], w2, y);
        y = fmaf(sx[li + 3], w3, y);
        y = fmaf(sx[li + 4], w4, y);
        y = fmaf(sx[li + 5], w5, y);
        y = fmaf(sx[li + 6], w6, y);
        const float s = 1.0f / (1.0f + expf(-y));
        xv[r] = sx[li + 3];
        sc[r] = s;
        v[r]  = __float_as_uint(s);     // positive: bit order == value order
        const int d = (int)(v[r] - LOBITS);
        bin[r] = d < 0 ? 0 : (d >> SH); // s < 1.0 => bin <= 16383
    }
    if (EPT == 2) *(float2*)(out + NELEM + e0) = make_float2(sc[0], sc[1]);
    else          out[NELEM + e0] = sc[0];

    // ---- global histogram: packed u16, 2 bins/word; halves never carry ----
    if (EPT == 2 && (bin[0] >> 1) == (bin[1] >> 1)) {
        const unsigned int add = ((bin[0] & 1) ? 0x10000u : 1u)
                               + ((bin[1] & 1) ? 0x10000u : 1u);
        atomicAdd(&g_hist[bin[0] >> 1], add);
    } else {
        #pragma unroll
        for (int r = 0; r < EPT; ++r)
            atomicAdd(&g_hist[bin[r] >> 1], (bin[r] & 1) ? 0x10000u : 1u);
    }

    cbar();   // ---- bar1: histogram complete ----

    // ---- redundant per-CTA prefix scan: 16 bins = 8 words = 2 LDG.128/thread ----
    {
        unsigned int h[16];
        {
            const uint4* hp = (const uint4*)(g_hist + tid * 8);
            const uint4 q0 = __ldcg(hp + 0), q1 = __ldcg(hp + 1);
            const unsigned int w_[8] = { q0.x, q0.y, q0.z, q0.w,
                                         q1.x, q1.y, q1.z, q1.w };
            #pragma unroll
            for (int k = 0; k < 8; ++k) {
                h[2 * k]     = w_[k] & 0xFFFFu;
                h[2 * k + 1] = w_[k] >> 16;
            }
        }
        unsigned int local = 0;
        #pragma unroll
        for (int q = 0; q < 16; ++q) local += h[q];

        unsigned int inc = local;
        #pragma unroll
        for (int o = 1; o < 32; o <<= 1) {
            unsigned int t = __shfl_up_sync(0xffffffffu, inc, o);
            if (lane >= o) inc += t;
        }
        if (lane == 31) sm_w[wid] = inc;
        __syncthreads();
        if (wid == 0) {
            unsigned int wsum = sm_w[lane];
            unsigned int winc = wsum;
            #pragma unroll
            for (int o = 1; o < 32; o <<= 1) {
                unsigned int t = __shfl_up_sync(0xffffffffu, winc, o);
                if (lane >= o) winc += t;
            }
            sm_w[lane] = winc - wsum;    // exclusive warp base
        }
        __syncthreads();
        const unsigned int base = sm_w[wid] + inc - local;

        if (base < KSEL && base + local >= KSEL) {   // exactly one thread; regs only
            unsigned int c = base;
            #pragma unroll
            for (int q = 0; q < 16; ++q) {
                if (c + h[q] >= KSEL) {
                    s_w0 = (unsigned)(tid * 16 + q) | ((KSEL - c) << 16);  // bstar|jkeep<<16
                    s_w1 = h[q];                                            // hcount
                    break;
                }
                c += h[q];
            }
        }
    }
    __syncthreads();
    const int          bstar  = (int)(s_w0 & 0xFFFFu);
    const unsigned int jkeep  = s_w0 >> 16;
    const unsigned int hcount = s_w1;

    // ---- register boundary candidates (expected ~10-30) ----
    bool anyb = false;
    #pragma unroll
    for (int r = 0; r < EPT; ++r) {
        if (bin[r] == bstar) {
            anyb = true;
            const unsigned int t = atomicAdd(&g_ccount, 1u);
            g_cand[t] = make_uint2(v[r], (unsigned)(e0 + r));
        }
    }

    cbar();   // ---- bar2: candidates + all hist reads complete ----

    // hist re-zero for next replay (all readers passed bar2)
    for (int i = tid; i < WORDS / NC; i += NT)
        g_hist[(int)blockIdx.x * (WORDS / NC) + i] = 0u;

    // ---- stage candidates into smem: warp 0, ONE parallel L2 round ----
    const bool staged = (hcount <= CANDS);
    if (staged && wid == 0) {
        for (unsigned int i = lane; i < hcount; i += 32)   // 32-wide MLP
            s_cand[i] = __ldcg(&g_cand[i]);
    }
    __syncthreads();

    // ---- exact stable rank among candidates (smem) + emit new_x ----
    float o[EPT];
    #pragma unroll
    for (int r = 0; r < EPT; ++r)
        o[r] = (bin[r] < bstar) ? xv[r] * (sc[r] + 1.0f) : 0.0f;

    if (anyb) {
        unsigned int rk[EPT];
        #pragma unroll
        for (int r = 0; r < EPT; ++r) rk[r] = 0;
        if (staged) {
            for (unsigned int c = 0; c < hcount; ++c) {    // LDS ~pipelined
                const uint2 cd = s_cand[c];
                #pragma unroll
                for (int r = 0; r < EPT; ++r)
                    rk[r] += (cd.x < v[r]) ||
                             (cd.x == v[r] && cd.y < (unsigned)(e0 + r));
            }
        } else {
            for (unsigned int c = 0; c < hcount; c += 4) { // gmem fallback
                uint2 cd[4];
                #pragma unroll
                for (int j = 0; j < 4; ++j) {
                    const unsigned int idx = (c + (unsigned)j < hcount) ? c + (unsigned)j : 0u;
                    cd[j] = __ldcg(&g_cand[idx]);
                }
                #pragma unroll
                for (int j = 0; j < 4; ++j) {
                    if (c + (unsigned)j < hcount) {
                        #pragma unroll
                        for (int r = 0; r < EPT; ++r)
                            rk[r] += (cd[j].x < v[r]) ||
                                     (cd[j].x == v[r] && cd[j].y < (unsigned)(e0 + r));
                    }
                }
            }
        }
        #pragma unroll
        for (int r = 0; r < EPT; ++r)
            if (bin[r] == bstar)
                o[r] = (rk[r] < jkeep) ? xv[r] * (sc[r] + 1.0f) : 0.0f;
    }
    if (EPT == 2) *(float2*)(out + e0) = make_float2(o[0], o[1]);
    else          out[e0] = o[0];
}

// 16-CTA variant: cluster dims supplied at launch (nonportable size)
__global__ __launch_bounds__(NT, 1)
void ca_c16(const float* __restrict__ x, const float* __restrict__ w7,
            float* __restrict__ out)
{
    ca_body<16>(x, w7, out);
}

// 8-CTA fallback: compile-time portable cluster
__global__ __launch_bounds__(NT, 1) __cluster_dims__(8, 1, 1)
void ca_c8(const float* __restrict__ x, const float* __restrict__ w7,
           float* __restrict__ out)
{
    ca_body<8>(x, w7, out);
}

extern "C" void kernel_launch(void* const* d_in, const int* in_sizes, int n_in,
                              void* d_out, int out_size)
{
    const float* x = (const float*)d_in[0];
    const float* w = (const float*)d_in[1];
    if (n_in >= 2 && in_sizes[0] == 7) {   // defensive input-order check
        const float* t = x; x = w; w = t;
    }
    float* out = (float*)d_out;

    // Nonportable cluster of 16 (pure queries — capture-safe, deterministic)
    cudaFuncSetAttribute(ca_c16, cudaFuncAttributeNonPortableClusterSizeAllowed, 1);

    cudaLaunchConfig_t cfg = {};
    cfg.gridDim          = dim3(16, 1, 1);
    cfg.blockDim         = dim3(NT, 1, 1);
    cfg.dynamicSmemBytes = 0;
    cfg.stream           = 0;
    cudaLaunchAttribute at[1];
    at[0].id = cudaLaunchAttributeClusterDimension;
    at[0].val.clusterDim.x = 16;
    at[0].val.clusterDim.y = 1;
    at[0].val.clusterDim.z = 1;
    cfg.attrs    = at;
    cfg.numAttrs = 1;

    int nclus = 0;
    cudaError_t q = cudaOccupancyMaxActiveClusters(&nclus, ca_c16, &cfg);
    if (q == cudaSuccess && nclus >= 1) {
        cudaLaunchKernelEx(&cfg, ca_c16, x, w, out);
    } else {
        cudaGetLastError();            // clear any sticky query error
        ca_c8<<<8, NT>>>(x, w, out);   // proven fallback
    }
}